// round 14
// baseline (speedup 1.0000x reference)
#include <cuda_runtime.h>
#include <cuda_fp16.h>
#include <cstdint>
#include <math.h>

#define H    2048
#define DIN  784
#define DOUT 10
#define NPAD1 896                 // DIN padded to a multiple of 128

// ---------------- scratch (device globals; no allocations allowed) ----------------
__device__ __align__(256) float g_u0[DIN], g_l0[DIN];
__device__ __align__(256) float g_ubL[3 * H], g_lbL[3 * H];
__device__ __align__(256) float g_sus[3 * H], g_sui[3 * H];
__device__ __align__(256) float g_sls[3 * H], g_sli[3 * H];
__device__ __align__(256) float g_pub[3 * H], g_plb[3 * H];
__device__ __align__(256) float g_lb4[DOUT];
__device__ __align__(256) float g_W0[(long)2 * H * NPAD1];    // final-GEMM fp32 output
__device__ __align__(256) float g_Bias[2 * H];                // running chain bias
// fp16 operand buffers (ping-pong A) + transposed fp16 weights (B)
__device__ __align__(256) __half g_A1[(long)2 * H * H];
__device__ __align__(256) __half g_A2[(long)2 * H * H];
__device__ __align__(256) __half g_T1f[(long)NPAD1 * H];
__device__ __align__(256) __half g_T2f[(long)H * H];
__device__ __align__(256) __half g_T3f[(long)H * H];

// ---------------- small device helpers ----------------
__device__ __forceinline__ float sigm_(float x) { return 1.0f / (1.0f + expf(-x)); }
__device__ __forceinline__ float spu_(float x) {
    return (x >= 0.0f) ? (x * x - 0.5f) : (sigm_(-x) - 1.0f);
}
__device__ __forceinline__ float warp_reduce(float v) {
#pragma unroll
    for (int o = 16; o > 0; o >>= 1) v += __shfl_down_sync(0xffffffffu, v, o);
    return v;
}
__device__ __forceinline__ uint32_t smem_u32(const void* p) {
    uint32_t a;
    asm("{ .reg .u64 t; cvta.to.shared.u64 t, %1; cvt.u32.u64 %0, t; }" : "=r"(a) : "l"(p));
    return a;
}
__device__ __forceinline__ void cp16(uint32_t dst, const void* src) {
    asm volatile("cp.async.cg.shared.global [%0], [%1], 16;" :: "r"(dst), "l"(src));
}
__device__ __forceinline__ void mma16816h(float* d, const uint32_t* a, const uint32_t* b) {
    asm volatile(
        "mma.sync.aligned.m16n8k16.row.col.f32.f16.f16.f32 "
        "{%0,%1,%2,%3}, {%4,%5,%6,%7}, {%8,%9}, {%0,%1,%2,%3};"
        : "+f"(d[0]), "+f"(d[1]), "+f"(d[2]), "+f"(d[3])
        : "r"(a[0]), "r"(a[1]), "r"(a[2]), "r"(a[3]), "r"(b[0]), "r"(b[1]));
}
__device__ __forceinline__ void ldsm_x4(uint32_t a, uint32_t* r) {
    asm volatile("ldmatrix.sync.aligned.m8n8.x4.shared.b16 {%0,%1,%2,%3}, [%4];"
                 : "=r"(r[0]), "=r"(r[1]), "=r"(r[2]), "=r"(r[3]) : "r"(a));
}
__device__ __forceinline__ void ldsm_x2(uint32_t a, uint32_t* r) {
    asm volatile("ldmatrix.sync.aligned.m8n8.x2.shared.b16 {%0,%1}, [%2];"
                 : "=r"(r[0]), "=r"(r[1]) : "r"(a));
}

// SPU relaxation analysis (exact reference math)
__device__ __forceinline__ void spu_analyze(float ux, float lx,
                                            float& usv, float& uiv,
                                            float& lsv, float& liv,
                                            float& nub, float& nlb) {
    float uy = spu_(ux), ly = spu_(lx);
    float sj = (uy - ly) / (ux - lx);
    float ij = uy - sj * ux;
    bool right = lx > 0.0f;
    bool left  = ux <= 0.0f;
    float mid = 0.5f * (ux + lx);
    float sp = 2.0f * mid, ip = -mid * mid - 0.5f;
    float sm = sigm_(mid);
    float ssm = -sm * (1.0f - sm), ism = -sm - ssm * mid;
    nub = fmaxf(uy, ly);
    if (right) {
        usv = sj; uiv = ij; lsv = sp; liv = ip; nlb = fminf(uy, ly);
    } else if (left) {
        usv = ssm; uiv = ism; lsv = sj; liv = ij; nlb = fminf(uy, ly);
    } else {
        nlb = -0.5f;
        float spu2 = 2.0f * ux, ipu = -ux * ux - 0.5f;
        float limit = spu2 * lx + ipu;
        float clm = (fabsf(lx) > ux) ? 1.0f : 0.0f;
        float clp = sigm_((clm - 0.5f) * 10.0f) * (ly - limit) + limit;
        if (clp < -0.5f) {
            float D = 4.0f * lx * lx - 4.0f * clp - 2.0f;
            float x2 = (2.0f * lx + sqrtf(fmaxf(D, 0.0f))) * 0.5f;
            lsv = 2.0f * x2; liv = -x2 * x2 - 0.5f;
        } else {
            lsv = (-0.5f - clp) / (0.0f - lx); liv = -0.5f;
        }
        float sl_ = sigm_(lx);
        float ssl = -sl_ * (1.0f - sl_), isl = -sl_ - ssl * lx;
        float stv = ssl * ux + isl - uy;
        if (stv > 0.0f) {
            float L = lx, R = 0.0f;
#pragma unroll
            for (int t = 0; t < 10; t++) {
                float m = 0.5f * (L + R);
                float s = sigm_(m);
                float sms = -s * (1.0f - s), ims = -s - sms * m;
                bool mask = (sms * ux + ims - uy) > 0.0f;
                L = mask ? m : L;
                R = mask ? R : m;
            }
            float scp = sigm_(-5.0f) * (L - lx) + lx;
            float sc = sigm_(scp);
            usv = -sc * (1.0f - sc);
            uiv = -sc - usv * scp;
        } else {
            usv = sj; uiv = ij;
        }
    }
}

// ---------------- elementwise kernels ----------------
__global__ void k_init_bounds(const float* __restrict__ in, const float* __restrict__ epsp,
                              float* __restrict__ u0, float* __restrict__ l0) {
    int i = blockIdx.x * blockDim.x + threadIdx.x;
    if (i >= DIN) return;
    float e = epsp[0];
    float u = fminf(in[i] + e, 1.0f);
    float l = fmaxf(in[i] - e, 0.0f);
    u0[i] = (u - 0.1307f) / 0.3081f;
    l0[i] = (l - 0.1307f) / 0.3081f;
}

// merged transpose to fp16 for all three weight matrices; blockIdx.z selects.
__global__ void k_transpose_all(const float* __restrict__ w1, const float* __restrict__ w2,
                                const float* __restrict__ w3,
                                __half* __restrict__ T1, __half* __restrict__ T2,
                                __half* __restrict__ T3) {
    __shared__ float t[32][33];
    int z = blockIdx.z;
    const float* W = (z == 0) ? w1 : (z == 1) ? w2 : w3;
    __half* T = (z == 0) ? T1 : (z == 1) ? T2 : T3;
    int N = (z == 0) ? DIN : H;
    int Npad = (z == 0) ? NPAD1 : H;
    int n0 = blockIdx.x * 32, k0 = blockIdx.y * 32;
    if (n0 >= Npad) return;
    int tx = threadIdx.x, ty = threadIdx.y;
#pragma unroll
    for (int i = 0; i < 4; i++) {
        int k = k0 + ty + 8 * i;
        int n = n0 + tx;
        t[ty + 8 * i][tx] = (n < N) ? W[(long)k * N + n] : 0.0f;
    }
    __syncthreads();
#pragma unroll
    for (int i = 0; i < 4; i++) {
        int n = n0 + ty + 8 * i;
        int k = k0 + tx;
        T[(long)n * H + k] = __float2half_rn(t[tx][ty + 8 * i]);
    }
}

// Layer 1 fused: affine interval over the input box + SPU analysis + post-SPU
// collapse (rawV == the interval values themselves at layer 1). Warp-per-row.
__global__ __launch_bounds__(256) void k_affine_spu(
    const float* __restrict__ W, const float* __restrict__ b,
    const float* __restrict__ u0, const float* __restrict__ l0,
    float* __restrict__ us, float* __restrict__ ui,
    float* __restrict__ ls, float* __restrict__ li,
    float* __restrict__ pub, float* __restrict__ plb) {
    int wid = threadIdx.x >> 5, lane = threadIdx.x & 31;
    int row = blockIdx.x * 8 + wid;
    if (row >= H) return;
    const float4* wr = (const float4*)(W + (long)row * DIN);
    const float4* u4 = (const float4*)u0;
    const float4* l4 = (const float4*)l0;
    float su = 0.0f, sl = 0.0f;
    for (int j = lane; j < DIN / 4; j += 32) {
        float4 w = wr[j], u = u4[j], l = l4[j];
        float p, n;
        p = fmaxf(w.x, 0.0f); n = fminf(w.x, 0.0f); su += p * u.x + n * l.x; sl += p * l.x + n * u.x;
        p = fmaxf(w.y, 0.0f); n = fminf(w.y, 0.0f); su += p * u.y + n * l.y; sl += p * l.y + n * u.y;
        p = fmaxf(w.z, 0.0f); n = fminf(w.z, 0.0f); su += p * u.z + n * l.z; sl += p * l.z + n * u.z;
        p = fmaxf(w.w, 0.0f); n = fminf(w.w, 0.0f); su += p * u.w + n * l.w; sl += p * l.w + n * u.w;
    }
    su = warp_reduce(su);
    sl = warp_reduce(sl);
    if (lane == 0) {
        float bb = b[row];
        float ub = su + bb, lb = sl + bb;
        float usv, uiv, lsv, liv, nub, nlb;
        spu_analyze(ub, lb, usv, uiv, lsv, liv, nub, nlb);
        us[row] = usv; ui[row] = uiv; ls[row] = lsv; li[row] = liv;
        float vu = (usv >= 0.0f) ? ub : lb;
        float vl = (lsv >= 0.0f) ? lb : ub;
        pub[row] = fminf(nub, usv * vu + uiv);
        plb[row] = fmaxf(nlb, lsv * vl + liv);
    }
}

// Fused layer start: interval bounds of W x + b AND chain-start column-scale
// (both chains), all from ONE pass over the layer weight matrix. Warp-per-row.
__global__ __launch_bounds__(256) void k_layer_start(
    const float* __restrict__ W, const float* __restrict__ bvec,
    const float* __restrict__ ub, const float* __restrict__ lb,
    const float* __restrict__ sus, const float* __restrict__ sui,
    const float* __restrict__ sls, const float* __restrict__ sli,
    const float* __restrict__ blayer,
    float* __restrict__ uo, float* __restrict__ lo,
    __half* __restrict__ A, float* __restrict__ Bias) {
    int wid = threadIdx.x >> 5, lane = threadIdx.x & 31;
    int row = blockIdx.x * 8 + wid;
    if (row >= H) return;
    const float4* wr = (const float4*)(W + (long)row * H);
    __half2* au = (__half2*)(A + (long)row * H);
    __half2* al = (__half2*)(A + (long)(row + H) * H);
    const float4* u4 = (const float4*)ub;
    const float4* l4 = (const float4*)lb;
    const float4* ps4 = (const float4*)sus;
    const float4* pi4 = (const float4*)sui;
    const float4* ns4 = (const float4*)sls;
    const float4* ni4 = (const float4*)sli;
    const float4* bl4 = (const float4*)blayer;
    float su = 0.0f, sl = 0.0f, accu = 0.0f, accl = 0.0f;
    for (int j = lane; j < H / 4; j += 32) {
        float4 w = wr[j], u = u4[j], l = l4[j];
        float4 psv = ps4[j], piv = pi4[j], nsv = ns4[j], niv = ni4[j], blv = bl4[j];
        float p, n, oux, ouy, ouz, ouw, olx, oly, olz, olw;
        p = fmaxf(w.x, 0.0f); n = fminf(w.x, 0.0f);
        su += p * u.x + n * l.x; sl += p * l.x + n * u.x;
        oux = p * psv.x + n * nsv.x; accu += p * piv.x + n * niv.x + oux * blv.x;
        olx = p * nsv.x + n * psv.x; accl += p * niv.x + n * piv.x + olx * blv.x;
        p = fmaxf(w.y, 0.0f); n = fminf(w.y, 0.0f);
        su += p * u.y + n * l.y; sl += p * l.y + n * u.y;
        ouy = p * psv.y + n * nsv.y; accu += p * piv.y + n * niv.y + ouy * blv.y;
        oly = p * nsv.y + n * psv.y; accl += p * niv.y + n * piv.y + oly * blv.y;
        p = fmaxf(w.z, 0.0f); n = fminf(w.z, 0.0f);
        su += p * u.z + n * l.z; sl += p * l.z + n * u.z;
        ouz = p * psv.z + n * nsv.z; accu += p * piv.z + n * niv.z + ouz * blv.z;
        olz = p * nsv.z + n * psv.z; accl += p * niv.z + n * piv.z + olz * blv.z;
        p = fmaxf(w.w, 0.0f); n = fminf(w.w, 0.0f);
        su += p * u.w + n * l.w; sl += p * l.w + n * u.w;
        ouw = p * psv.w + n * nsv.w; accu += p * piv.w + n * niv.w + ouw * blv.w;
        olw = p * nsv.w + n * psv.w; accl += p * niv.w + n * piv.w + olw * blv.w;
        au[2 * j]     = __floats2half2_rn(oux, ouy);
        au[2 * j + 1] = __floats2half2_rn(ouz, ouw);
        al[2 * j]     = __floats2half2_rn(olx, oly);
        al[2 * j + 1] = __floats2half2_rn(olz, olw);
    }
    su = warp_reduce(su);
    sl = warp_reduce(sl);
    accu = warp_reduce(accu);
    accl = warp_reduce(accl);
    if (lane == 0) {
        float bb = bvec[row];
        uo[row] = su + bb;
        lo[row] = sl + bb;
        Bias[row] = bb + accu;
        Bias[row + H] = bb + accl;
    }
}

// Fused chain end (layers 2/3): final interval evaluation of BOTH chains for one
// output neuron (rows orow / orow+H of W0), bound refinement, SPU analysis, and
// post-SPU collapse — one kernel, warp-per-neuron.
__global__ __launch_bounds__(256) void k_interval_spu(
    const float* __restrict__ W, int ld, const float* __restrict__ bias,
    const float* __restrict__ u0, const float* __restrict__ l0,
    const float* __restrict__ ubl, const float* __restrict__ lbl,
    float* __restrict__ us, float* __restrict__ ui,
    float* __restrict__ ls, float* __restrict__ li,
    float* __restrict__ pub, float* __restrict__ plb) {
    int wid = threadIdx.x >> 5, lane = threadIdx.x & 31;
    int orow = blockIdx.x * 8 + wid;
    if (orow >= H) return;
    const float4* wu = (const float4*)(W + (long)orow * ld);
    const float4* wl = (const float4*)(W + (long)(orow + H) * ld);
    const float4* u4 = (const float4*)u0;
    const float4* l4 = (const float4*)l0;
    float accu = 0.0f, accl = 0.0f;
    for (int j = lane; j < DIN / 4; j += 32) {
        float4 a = wu[j], b = wl[j];
        float4 uv = u4[j], lv = l4[j];
        accu += fmaxf(a.x, 0.0f) * uv.x + fminf(a.x, 0.0f) * lv.x;
        accu += fmaxf(a.y, 0.0f) * uv.y + fminf(a.y, 0.0f) * lv.y;
        accu += fmaxf(a.z, 0.0f) * uv.z + fminf(a.z, 0.0f) * lv.z;
        accu += fmaxf(a.w, 0.0f) * uv.w + fminf(a.w, 0.0f) * lv.w;
        accl += fmaxf(b.x, 0.0f) * lv.x + fminf(b.x, 0.0f) * uv.x;
        accl += fmaxf(b.y, 0.0f) * lv.y + fminf(b.y, 0.0f) * uv.y;
        accl += fmaxf(b.z, 0.0f) * lv.z + fminf(b.z, 0.0f) * uv.z;
        accl += fmaxf(b.w, 0.0f) * lv.w + fminf(b.w, 0.0f) * uv.w;
    }
    accu = warp_reduce(accu);
    accl = warp_reduce(accl);
    if (lane == 0) {
        float vu = accu + bias[orow];
        float vl = accl + bias[orow + H];
        float ub = fminf(ubl[orow], vu);
        float lb = fmaxf(lbl[orow], vl);
        float usv, uiv, lsv, liv, nub, nlb;
        spu_analyze(ub, lb, usv, uiv, lsv, liv, nub, nlb);
        us[orow] = usv; ui[orow] = uiv; ls[orow] = lsv; li[orow] = liv;
        float pvu = (usv >= 0.0f) ? vu : vl;
        float pvl = (lsv >= 0.0f) ? vl : vu;
        pub[orow] = fminf(nub, usv * pvu + uiv);
        plb[orow] = fmaxf(nlb, lsv * pvl + liv);
    }
}

// Layer 4 fused start: lower interval bound (LB4 init) + lower-chain colscale
// from ONE pass over w4. Warp-per-row, M=DOUT rows, all-lower chain.
__global__ __launch_bounds__(256) void k_affine_cs4(
    const float* __restrict__ W, const float* __restrict__ bvec,
    const float* __restrict__ ub, const float* __restrict__ lb,
    const float* __restrict__ sus, const float* __restrict__ sui,
    const float* __restrict__ sls, const float* __restrict__ sli,
    const float* __restrict__ blayer,
    __half* __restrict__ A, float* __restrict__ Bias, float* __restrict__ lb4) {
    int wid = threadIdx.x >> 5, lane = threadIdx.x & 31;
    int row = blockIdx.x * 8 + wid;
    if (row >= DOUT) return;
    const float4* wr = (const float4*)(W + (long)row * H);
    __half2* ah = (__half2*)(A + (long)row * H);
    const float4* u4 = (const float4*)ub;
    const float4* l4 = (const float4*)lb;
    const float4* ps = (const float4*)sls;   // lower chain
    const float4* pi = (const float4*)sli;
    const float4* ns = (const float4*)sus;
    const float4* ni = (const float4*)sui;
    const float4* bl = (const float4*)blayer;
    float sl = 0.0f, acc = 0.0f;
    for (int j = lane; j < H / 4; j += 32) {
        float4 w = wr[j], u = u4[j], l = l4[j];
        float4 psv = ps[j], piv = pi[j], nsv = ns[j], niv = ni[j], blv = bl[j];
        float4 o;
        float p, n;
        p = fmaxf(w.x, 0.0f); n = fminf(w.x, 0.0f); sl += p * l.x + n * u.x;
        o.x = p * psv.x + n * nsv.x; acc += p * piv.x + n * niv.x + o.x * blv.x;
        p = fmaxf(w.y, 0.0f); n = fminf(w.y, 0.0f); sl += p * l.y + n * u.y;
        o.y = p * psv.y + n * nsv.y; acc += p * piv.y + n * niv.y + o.y * blv.y;
        p = fmaxf(w.z, 0.0f); n = fminf(w.z, 0.0f); sl += p * l.z + n * u.z;
        o.z = p * psv.z + n * nsv.z; acc += p * piv.z + n * niv.z + o.z * blv.z;
        p = fmaxf(w.w, 0.0f); n = fminf(w.w, 0.0f); sl += p * l.w + n * u.w;
        o.w = p * psv.w + n * nsv.w; acc += p * piv.w + n * niv.w + o.w * blv.w;
        ah[2 * j]     = __floats2half2_rn(o.x, o.y);
        ah[2 * j + 1] = __floats2half2_rn(o.z, o.w);
    }
    sl = warp_reduce(sl);
    acc = warp_reduce(acc);
    if (lane == 0) {
        float bb = bvec[row];
        lb4[row] = sl + bb;
        Bias[row] = bb + acc;
    }
}

// Final interval evaluation at the input layer (layer-4 chain end); warp-per-row.
__global__ __launch_bounds__(256) void k_interval_f4(
    const float* __restrict__ W, int ld, const float* __restrict__ bias,
    const float* __restrict__ u0, const float* __restrict__ l0,
    float* __restrict__ lbio) {
    int wid = threadIdx.x >> 5, lane = threadIdx.x & 31;
    int row = blockIdx.x * 8 + wid;
    if (row >= DOUT) return;
    const float4* wr = (const float4*)(W + (long)row * ld);
    const float4* a4 = (const float4*)l0;
    const float4* c4p = (const float4*)u0;
    float acc = 0.0f;
    for (int j = lane; j < DIN / 4; j += 32) {
        float4 w = wr[j];
        float4 av = a4[j], cv = c4p[j];
        acc += fmaxf(w.x, 0.0f) * av.x + fminf(w.x, 0.0f) * cv.x;
        acc += fmaxf(w.y, 0.0f) * av.y + fminf(w.y, 0.0f) * cv.y;
        acc += fmaxf(w.z, 0.0f) * av.z + fminf(w.z, 0.0f) * cv.z;
        acc += fmaxf(w.w, 0.0f) * av.w + fminf(w.w, 0.0f) * cv.w;
    }
    acc = warp_reduce(acc);
    if (lane == 0) {
        float v = acc + bias[row];
        lbio[row] = fmaxf(lbio[row], v);
    }
}

// ---------------- fp16 GEMM via mma.sync (HMMA), 3-stage cp.async pipeline ------
// (exact R11/R13 configuration — known-good, do not perturb)
#define GSTRIDE 80
#define TILEB   (128 * GSTRIDE)
#define STAGEB  (2 * TILEB)            // A | B
#define NSTAGE  3
#define GEMM_SMEM (NSTAGE * STAGEB)    // 61440

struct GemmCtx {
    float acc[4][4][4];
    int rowBase, colBase, mbase, nbase, lr, lc2;
};

__device__ __forceinline__ void gemm_mainloop(
    GemmCtx& cx, char* dynsm,
    const __half* __restrict__ A, const __half* __restrict__ B, int M) {
    const int tid = threadIdx.x;
    const int wid = tid >> 5;
    const int lane = tid & 31;
    const uint32_t smbase = smem_u32(dynsm);
    const int wm = wid & 1, wn = wid >> 1;
    cx.mbase = wm * 64; cx.nbase = wn * 32;
    cx.lr = lane >> 2; cx.lc2 = 2 * (lane & 3);
#pragma unroll
    for (int mi = 0; mi < 4; mi++)
#pragma unroll
        for (int ni = 0; ni < 4; ni++)
#pragma unroll
            for (int t = 0; t < 4; t++) cx.acc[mi][ni][t] = 0.0f;

    const uint32_t aRowOff = (uint32_t)(cx.mbase + (lane & 15)) * GSTRIDE + (lane >> 4) * 16;
    const uint32_t bRowOff = (uint32_t)(cx.nbase + (lane & 7)) * GSTRIDE + ((lane >> 3) & 1) * 16;

    auto issue = [&](int c) {
        const int st = c % NSTAGE;
        const uint32_t base = smbase + st * STAGEB;
        const long k0 = (long)c * 32;
#pragma unroll
        for (int p = 0; p < 2; p++) {
            int u = tid + p * 256;
            int row = u >> 2, seg = u & 3;
            uint32_t so = base + row * GSTRIDE + seg * 16;
            long ka = k0 + seg * 8;
            int grow = cx.rowBase + row; if (grow > M - 1) grow = M - 1;
            cp16(so,         A + (long)grow * H + ka);
            int gn = cx.colBase + row;
            cp16(so + TILEB, B + (long)gn * H + ka);
        }
        asm volatile("cp.async.commit_group;");
    };

    const int NK = H / 32;
    issue(0);
    issue(1);
    for (int c = 0; c < NK; ++c) {
        if (c + 2 < NK) {
            issue(c + 2);
            asm volatile("cp.async.wait_group 2;");
        } else if (c + 1 < NK) {
            asm volatile("cp.async.wait_group 1;");
        } else {
            asm volatile("cp.async.wait_group 0;");
        }
        __syncthreads();
        const uint32_t sbu = smbase + (c % NSTAGE) * STAGEB;
        const uint32_t sAu = sbu + aRowOff;
        const uint32_t sBu = sbu + TILEB + bRowOff;
#pragma unroll
        for (int kk = 0; kk < 32; kk += 16) {
            const uint32_t kb = (uint32_t)(kk * 2);
            uint32_t bh[4][2];
#pragma unroll
            for (int ni = 0; ni < 4; ni++)
                ldsm_x2(sBu + (uint32_t)(ni * 8) * GSTRIDE + kb, bh[ni]);
#pragma unroll
            for (int mi = 0; mi < 4; mi++) {
                uint32_t ah[4];
                ldsm_x4(sAu + (uint32_t)(mi * 16) * GSTRIDE + kb, ah);
#pragma unroll
                for (int ni = 0; ni < 4; ni++)
                    mma16816h(cx.acc[mi][ni], ah, bh[ni]);
            }
        }
        __syncthreads();
    }
}

// Plain epilogue: fp32 C (used for the last GEMM of a chain).
__global__ __launch_bounds__(256) void gemm_mma(
    const __half* __restrict__ A, const __half* __restrict__ B,
    float* __restrict__ C, int M, int ldc) {
    extern __shared__ char dynsm[];
    GemmCtx cx;
    cx.rowBase = blockIdx.y * 128;
    cx.colBase = blockIdx.x * 128;
    gemm_mainloop(cx, dynsm, A, B, M);
#pragma unroll
    for (int mi = 0; mi < 4; mi++) {
        int gr0 = cx.rowBase + cx.mbase + mi * 16 + cx.lr;
#pragma unroll
        for (int ni = 0; ni < 4; ni++) {
            int gc = cx.colBase + cx.nbase + ni * 8 + cx.lc2;
            if (gr0 < M) {
                float2 v = make_float2(cx.acc[mi][ni][0], cx.acc[mi][ni][1]);
                *(float2*)(C + (long)gr0 * ldc + gc) = v;
            }
            if (gr0 + 8 < M) {
                float2 v = make_float2(cx.acc[mi][ni][2], cx.acc[mi][ni][3]);
                *(float2*)(C + (long)(gr0 + 8) * ldc + gc) = v;
            }
        }
    }
}

// Fused colscale epilogue: applies the next SPU diagonal pass to the accumulators,
// writes the fp16 A operand for the next GEMM, and atomically accumulates the
// per-row bias contribution (quad-reduced) into the running chain bias.
__global__ __launch_bounds__(256) void gemm_mma_cs(
    const __half* __restrict__ A, const __half* __restrict__ B,
    const float* __restrict__ sus, const float* __restrict__ sui,
    const float* __restrict__ sls, const float* __restrict__ sli,
    const float* __restrict__ blayer,
    __half* __restrict__ Ao, float* __restrict__ Bias, int M, int Mu) {
    extern __shared__ char dynsm[];
    GemmCtx cx;
    cx.rowBase = blockIdx.y * 128;
    cx.colBase = blockIdx.x * 128;
    gemm_mainloop(cx, dynsm, A, B, M);

    const bool up = cx.rowBase < Mu;    // Mu multiple of 128 (or 0) -> CTA-uniform
    const float* ps = up ? sus : sls;
    const float* pi = up ? sui : sli;
    const float* ns = up ? sls : sus;
    const float* ni_ = up ? sli : sui;
    const int lane = threadIdx.x & 31;

#pragma unroll
    for (int mi = 0; mi < 4; mi++) {
        int gr0 = cx.rowBase + cx.mbase + mi * 16 + cx.lr;
        int gr1 = gr0 + 8;
        float rs0 = 0.0f, rs1 = 0.0f;
#pragma unroll
        for (int ni = 0; ni < 4; ni++) {
            int gc = cx.colBase + cx.nbase + ni * 8 + cx.lc2;
            float s0 = ps[gc], s1 = ps[gc + 1];
            float i0 = pi[gc], i1 = pi[gc + 1];
            float t0 = ns[gc], t1 = ns[gc + 1];
            float u0v = ni_[gc], u1v = ni_[gc + 1];
            float b0 = blayer[gc], b1 = blayer[gc + 1];
            {
                float v0 = cx.acc[mi][ni][0], v1 = cx.acc[mi][ni][1];
                float p0 = fmaxf(v0, 0.0f), n0 = fminf(v0, 0.0f);
                float p1 = fmaxf(v1, 0.0f), n1 = fminf(v1, 0.0f);
                float o0 = p0 * s0 + n0 * t0;
                float o1 = p1 * s1 + n1 * t1;
                rs0 += p0 * i0 + n0 * u0v + o0 * b0 + p1 * i1 + n1 * u1v + o1 * b1;
                if (gr0 < M)
                    *(__half2*)(Ao + (long)gr0 * H + gc) = __floats2half2_rn(o0, o1);
            }
            {
                float v0 = cx.acc[mi][ni][2], v1 = cx.acc[mi][ni][3];
                float p0 = fmaxf(v0, 0.0f), n0 = fminf(v0, 0.0f);
                float p1 = fmaxf(v1, 0.0f), n1 = fminf(v1, 0.0f);
                float o0 = p0 * s0 + n0 * t0;
                float o1 = p1 * s1 + n1 * t1;
                rs1 += p0 * i0 + n0 * u0v + o0 * b0 + p1 * i1 + n1 * u1v + o1 * b1;
                if (gr1 < M)
                    *(__half2*)(Ao + (long)gr1 * H + gc) = __floats2half2_rn(o0, o1);
            }
        }
        rs0 += __shfl_xor_sync(0xffffffffu, rs0, 1);
        rs0 += __shfl_xor_sync(0xffffffffu, rs0, 2);
        rs1 += __shfl_xor_sync(0xffffffffu, rs1, 1);
        rs1 += __shfl_xor_sync(0xffffffffu, rs1, 2);
        if ((lane & 3) == 0) {
            if (gr0 < M) atomicAdd(Bias + gr0, rs0);
            if (gr1 < M) atomicAdd(Bias + gr1, rs1);
        }
    }
}

__global__ void k_final_min(const float* __restrict__ lb4, float* __restrict__ out) {
    if (threadIdx.x == 0) {
        float m = lb4[0];
#pragma unroll
        for (int i = 1; i < DOUT; i++) m = fminf(m, lb4[i]);
        out[0] = m;
    }
}

// ---------------- host orchestration ----------------
extern "C" void kernel_launch(void* const* d_in, const int* in_sizes, int n_in,
                              void* d_out, int out_size) {
    (void)in_sizes; (void)n_in; (void)out_size;
    const float* inputs = (const float*)d_in[0];
    const float* eps    = (const float*)d_in[1];
    const float* w1 = (const float*)d_in[2]; const float* b1 = (const float*)d_in[3];
    const float* w2 = (const float*)d_in[4]; const float* b2 = (const float*)d_in[5];
    const float* w3 = (const float*)d_in[6]; const float* b3 = (const float*)d_in[7];
    const float* w4 = (const float*)d_in[8]; const float* b4 = (const float*)d_in[9];
    float* out = (float*)d_out;

    cudaFuncSetAttribute(gemm_mma,    cudaFuncAttributeMaxDynamicSharedMemorySize, GEMM_SMEM);
    cudaFuncSetAttribute(gemm_mma_cs, cudaFuncAttributeMaxDynamicSharedMemorySize, GEMM_SMEM);

    float *U0, *L0, *UBL, *LBL, *SUS, *SUI, *SLS, *SLI, *PUB, *PLB, *LB4;
    float *W0, *BIAS;
    __half *A1, *A2, *T1F, *T2F, *T3F;
    cudaGetSymbolAddress((void**)&U0, g_u0);
    cudaGetSymbolAddress((void**)&L0, g_l0);
    cudaGetSymbolAddress((void**)&UBL, g_ubL);
    cudaGetSymbolAddress((void**)&LBL, g_lbL);
    cudaGetSymbolAddress((void**)&SUS, g_sus);
    cudaGetSymbolAddress((void**)&SUI, g_sui);
    cudaGetSymbolAddress((void**)&SLS, g_sls);
    cudaGetSymbolAddress((void**)&SLI, g_sli);
    cudaGetSymbolAddress((void**)&PUB, g_pub);
    cudaGetSymbolAddress((void**)&PLB, g_plb);
    cudaGetSymbolAddress((void**)&LB4, g_lb4);
    cudaGetSymbolAddress((void**)&W0, g_W0);
    cudaGetSymbolAddress((void**)&BIAS, g_Bias);
    cudaGetSymbolAddress((void**)&A1, g_A1);
    cudaGetSymbolAddress((void**)&A2, g_A2);
    cudaGetSymbolAddress((void**)&T1F, g_T1f);
    cudaGetSymbolAddress((void**)&T2F, g_T2f);
    cudaGetSymbolAddress((void**)&T3F, g_T3f);

    // transposed fp16 weights (B operands) — one merged launch
    k_transpose_all<<<dim3(64, 64, 3), dim3(32, 8)>>>(w1, w2, w3, T1F, T2F, T3F);

    // input box (normalized)
    k_init_bounds<<<(DIN + 255) / 256, 256>>>(inputs, eps, U0, L0);

    // ---- layer 1 (fused affine interval + SPU + post collapse) ----
    k_affine_spu<<<H / 8, 256>>>(w1, b1, U0, L0,
                                 SUS + 0 * H, SUI + 0 * H, SLS + 0 * H, SLI + 0 * H,
                                 PUB + 0 * H, PLB + 0 * H);

    // ---- layer 2 ----
    k_layer_start<<<H / 8, 256>>>(w2, b2, PUB + 0 * H, PLB + 0 * H,
                                  SUS + 0 * H, SUI + 0 * H, SLS + 0 * H, SLI + 0 * H,
                                  b1, UBL + 1 * H, LBL + 1 * H, A1, BIAS);
    {
        dim3 g(NPAD1 / 128, (2 * H) / 128);
        gemm_mma<<<g, 256, GEMM_SMEM>>>(A1, T1F, W0, 2 * H, NPAD1);
    }
    k_interval_spu<<<H / 8, 256>>>(W0, NPAD1, BIAS, U0, L0,
                                   UBL + 1 * H, LBL + 1 * H,
                                   SUS + 1 * H, SUI + 1 * H, SLS + 1 * H, SLI + 1 * H,
                                   PUB + 1 * H, PLB + 1 * H);

    // ---- layer 3 ----
    k_layer_start<<<H / 8, 256>>>(w3, b3, PUB + 1 * H, PLB + 1 * H,
                                  SUS + 1 * H, SUI + 1 * H, SLS + 1 * H, SLI + 1 * H,
                                  b2, UBL + 2 * H, LBL + 2 * H, A1, BIAS);
    {
        dim3 g(H / 128, (2 * H) / 128);
        gemm_mma_cs<<<g, 256, GEMM_SMEM>>>(A1, T2F,
                                           SUS + 0 * H, SUI + 0 * H, SLS + 0 * H, SLI + 0 * H,
                                           b1, A2, BIAS, 2 * H, H);
        dim3 g2(NPAD1 / 128, (2 * H) / 128);
        gemm_mma<<<g2, 256, GEMM_SMEM>>>(A2, T1F, W0, 2 * H, NPAD1);
    }
    k_interval_spu<<<H / 8, 256>>>(W0, NPAD1, BIAS, U0, L0,
                                   UBL + 2 * H, LBL + 2 * H,
                                   SUS + 2 * H, SUI + 2 * H, SLS + 2 * H, SLI + 2 * H,
                                   PUB + 2 * H, PLB + 2 * H);

    // ---- layer 4 (only the lower bound matters for the output) ----
    k_affine_cs4<<<(DOUT + 7) / 8, 256>>>(w4, b4, PUB + 2 * H, PLB + 2 * H,
                                          SUS + 2 * H, SUI + 2 * H, SLS + 2 * H, SLI + 2 * H,
                                          b3, A1, BIAS, LB4);
    {
        dim3 g(H / 128, 1);
        gemm_mma_cs<<<g, 256, GEMM_SMEM>>>(A1, T3F,
                                           SUS + 1 * H, SUI + 1 * H, SLS + 1 * H, SLI + 1 * H,
                                           b2, A2, BIAS, DOUT, 0);
        gemm_mma_cs<<<g, 256, GEMM_SMEM>>>(A2, T2F,
                                           SUS + 0 * H, SUI + 0 * H, SLS + 0 * H, SLI + 0 * H,
                                           b1, A1, BIAS, DOUT, 0);
        dim3 g2(NPAD1 / 128, 1);
        gemm_mma<<<g2, 256, GEMM_SMEM>>>(A1, T1F, W0, DOUT, NPAD1);
    }
    k_interval_f4<<<(DOUT + 7) / 8, 256>>>(W0, NPAD1, BIAS, U0, L0, LB4);

    k_final_min<<<1, 32>>>(LB4, out);
}

// round 15
// speedup vs baseline: 1.0753x; 1.0753x over previous
#include <cuda_runtime.h>
#include <cuda_fp16.h>
#include <cstdint>
#include <math.h>

#define H    2048
#define DIN  784
#define DOUT 10
#define NPAD1 896                 // DIN padded to a multiple of 128

// ---------------- scratch (device globals; no allocations allowed) ----------------
__device__ __align__(256) float g_u0[DIN], g_l0[DIN];
__device__ __align__(256) float g_ubL[3 * H], g_lbL[3 * H];
__device__ __align__(256) float g_sus[3 * H], g_sui[3 * H];
__device__ __align__(256) float g_sls[3 * H], g_sli[3 * H];
__device__ __align__(256) float g_pub[3 * H], g_plb[3 * H];
__device__ __align__(256) float g_lb4[DOUT];
__device__ __align__(256) float g_W0[(long)2 * H * NPAD1];    // final-GEMM fp32 output
__device__ __align__(256) float g_Bias[2 * H];                // running chain bias
// fp16 operand buffers (ping-pong A) + transposed fp16 weights (B)
__device__ __align__(256) __half g_A1[(long)2 * H * H];
__device__ __align__(256) __half g_A2[(long)2 * H * H];
__device__ __align__(256) __half g_T1f[(long)NPAD1 * H];
__device__ __align__(256) __half g_T2f[(long)H * H];
__device__ __align__(256) __half g_T3f[(long)H * H];

// ---------------- small device helpers ----------------
__device__ __forceinline__ float sigm_(float x) { return 1.0f / (1.0f + expf(-x)); }
__device__ __forceinline__ float spu_(float x) {
    return (x >= 0.0f) ? (x * x - 0.5f) : (sigm_(-x) - 1.0f);
}
__device__ __forceinline__ float warp_reduce(float v) {
#pragma unroll
    for (int o = 16; o > 0; o >>= 1) v += __shfl_down_sync(0xffffffffu, v, o);
    return v;
}
__device__ __forceinline__ uint32_t smem_u32(const void* p) {
    uint32_t a;
    asm("{ .reg .u64 t; cvta.to.shared.u64 t, %1; cvt.u32.u64 %0, t; }" : "=r"(a) : "l"(p));
    return a;
}
__device__ __forceinline__ void cp16(uint32_t dst, const void* src) {
    asm volatile("cp.async.cg.shared.global [%0], [%1], 16;" :: "r"(dst), "l"(src));
}
__device__ __forceinline__ void mma16816h(float* d, const uint32_t* a, const uint32_t* b) {
    asm volatile(
        "mma.sync.aligned.m16n8k16.row.col.f32.f16.f16.f32 "
        "{%0,%1,%2,%3}, {%4,%5,%6,%7}, {%8,%9}, {%0,%1,%2,%3};"
        : "+f"(d[0]), "+f"(d[1]), "+f"(d[2]), "+f"(d[3])
        : "r"(a[0]), "r"(a[1]), "r"(a[2]), "r"(a[3]), "r"(b[0]), "r"(b[1]));
}
__device__ __forceinline__ void ldsm_x4(uint32_t a, uint32_t* r) {
    asm volatile("ldmatrix.sync.aligned.m8n8.x4.shared.b16 {%0,%1,%2,%3}, [%4];"
                 : "=r"(r[0]), "=r"(r[1]), "=r"(r[2]), "=r"(r[3]) : "r"(a));
}
__device__ __forceinline__ void ldsm_x2(uint32_t a, uint32_t* r) {
    asm volatile("ldmatrix.sync.aligned.m8n8.x2.shared.b16 {%0,%1}, [%2];"
                 : "=r"(r[0]), "=r"(r[1]) : "r"(a));
}

// SPU relaxation analysis (exact reference math)
__device__ __forceinline__ void spu_analyze(float ux, float lx,
                                            float& usv, float& uiv,
                                            float& lsv, float& liv,
                                            float& nub, float& nlb) {
    float uy = spu_(ux), ly = spu_(lx);
    float sj = (uy - ly) / (ux - lx);
    float ij = uy - sj * ux;
    bool right = lx > 0.0f;
    bool left  = ux <= 0.0f;
    float mid = 0.5f * (ux + lx);
    float sp = 2.0f * mid, ip = -mid * mid - 0.5f;
    float sm = sigm_(mid);
    float ssm = -sm * (1.0f - sm), ism = -sm - ssm * mid;
    nub = fmaxf(uy, ly);
    if (right) {
        usv = sj; uiv = ij; lsv = sp; liv = ip; nlb = fminf(uy, ly);
    } else if (left) {
        usv = ssm; uiv = ism; lsv = sj; liv = ij; nlb = fminf(uy, ly);
    } else {
        nlb = -0.5f;
        float spu2 = 2.0f * ux, ipu = -ux * ux - 0.5f;
        float limit = spu2 * lx + ipu;
        float clm = (fabsf(lx) > ux) ? 1.0f : 0.0f;
        float clp = sigm_((clm - 0.5f) * 10.0f) * (ly - limit) + limit;
        if (clp < -0.5f) {
            float D = 4.0f * lx * lx - 4.0f * clp - 2.0f;
            float x2 = (2.0f * lx + sqrtf(fmaxf(D, 0.0f))) * 0.5f;
            lsv = 2.0f * x2; liv = -x2 * x2 - 0.5f;
        } else {
            lsv = (-0.5f - clp) / (0.0f - lx); liv = -0.5f;
        }
        float sl_ = sigm_(lx);
        float ssl = -sl_ * (1.0f - sl_), isl = -sl_ - ssl * lx;
        float stv = ssl * ux + isl - uy;
        if (stv > 0.0f) {
            float L = lx, R = 0.0f;
#pragma unroll
            for (int t = 0; t < 10; t++) {
                float m = 0.5f * (L + R);
                float s = sigm_(m);
                float sms = -s * (1.0f - s), ims = -s - sms * m;
                bool mask = (sms * ux + ims - uy) > 0.0f;
                L = mask ? m : L;
                R = mask ? R : m;
            }
            float scp = sigm_(-5.0f) * (L - lx) + lx;
            float sc = sigm_(scp);
            usv = -sc * (1.0f - sc);
            uiv = -sc - usv * scp;
        } else {
            usv = sj; uiv = ij;
        }
    }
}

// ---------------- elementwise kernels ----------------
__global__ void k_init_bounds(const float* __restrict__ in, const float* __restrict__ epsp,
                              float* __restrict__ u0, float* __restrict__ l0) {
    int i = blockIdx.x * blockDim.x + threadIdx.x;
    if (i >= DIN) return;
    float e = epsp[0];
    float u = fminf(in[i] + e, 1.0f);
    float l = fmaxf(in[i] - e, 0.0f);
    u0[i] = (u - 0.1307f) / 0.3081f;
    l0[i] = (l - 0.1307f) / 0.3081f;
}

// merged transpose to fp16 for all three weight matrices; blockIdx.z selects.
__global__ void k_transpose_all(const float* __restrict__ w1, const float* __restrict__ w2,
                                const float* __restrict__ w3,
                                __half* __restrict__ T1, __half* __restrict__ T2,
                                __half* __restrict__ T3) {
    __shared__ float t[32][33];
    int z = blockIdx.z;
    const float* W = (z == 0) ? w1 : (z == 1) ? w2 : w3;
    __half* T = (z == 0) ? T1 : (z == 1) ? T2 : T3;
    int N = (z == 0) ? DIN : H;
    int Npad = (z == 0) ? NPAD1 : H;
    int n0 = blockIdx.x * 32, k0 = blockIdx.y * 32;
    if (n0 >= Npad) return;
    int tx = threadIdx.x, ty = threadIdx.y;
#pragma unroll
    for (int i = 0; i < 4; i++) {
        int k = k0 + ty + 8 * i;
        int n = n0 + tx;
        t[ty + 8 * i][tx] = (n < N) ? W[(long)k * N + n] : 0.0f;
    }
    __syncthreads();
#pragma unroll
    for (int i = 0; i < 4; i++) {
        int n = n0 + ty + 8 * i;
        int k = k0 + tx;
        T[(long)n * H + k] = __float2half_rn(t[tx][ty + 8 * i]);
    }
}

// Layer 1 fused: affine interval + SPU + post collapse. TWO warps per row
// (interleaved halves), 4 rows per 256-thread block; smem combine.
__global__ __launch_bounds__(256) void k_affine_spu(
    const float* __restrict__ W, const float* __restrict__ b,
    const float* __restrict__ u0, const float* __restrict__ l0,
    float* __restrict__ us, float* __restrict__ ui,
    float* __restrict__ ls, float* __restrict__ li,
    float* __restrict__ pub, float* __restrict__ plb) {
    int wid = threadIdx.x >> 5, lane = threadIdx.x & 31;
    int rl = wid >> 1, half = wid & 1;
    int row = blockIdx.x * 4 + rl;               // grid exact: H/4 blocks
    __shared__ float red[4][4];                  // [rowLocal][half*2 + {u,l}]
    const float4* wr = (const float4*)(W + (long)row * DIN);
    const float4* u4 = (const float4*)u0;
    const float4* l4 = (const float4*)l0;
    float su = 0.0f, sl = 0.0f;
    for (int j = lane + half * 32; j < DIN / 4; j += 64) {
        float4 w = wr[j], u = u4[j], l = l4[j];
        float p, n;
        p = fmaxf(w.x, 0.0f); n = fminf(w.x, 0.0f); su += p * u.x + n * l.x; sl += p * l.x + n * u.x;
        p = fmaxf(w.y, 0.0f); n = fminf(w.y, 0.0f); su += p * u.y + n * l.y; sl += p * l.y + n * u.y;
        p = fmaxf(w.z, 0.0f); n = fminf(w.z, 0.0f); su += p * u.z + n * l.z; sl += p * l.z + n * u.z;
        p = fmaxf(w.w, 0.0f); n = fminf(w.w, 0.0f); su += p * u.w + n * l.w; sl += p * l.w + n * u.w;
    }
    su = warp_reduce(su);
    sl = warp_reduce(sl);
    if (lane == 0) { red[rl][half * 2] = su; red[rl][half * 2 + 1] = sl; }
    __syncthreads();
    if (half == 0 && lane == 0) {
        float bb = b[row];
        float ub = red[rl][0] + red[rl][2] + bb;
        float lb = red[rl][1] + red[rl][3] + bb;
        float usv, uiv, lsv, liv, nub, nlb;
        spu_analyze(ub, lb, usv, uiv, lsv, liv, nub, nlb);
        us[row] = usv; ui[row] = uiv; ls[row] = lsv; li[row] = liv;
        float vu = (usv >= 0.0f) ? ub : lb;
        float vl = (lsv >= 0.0f) ? lb : ub;
        pub[row] = fminf(nub, usv * vu + uiv);
        plb[row] = fmaxf(nlb, lsv * vl + liv);
    }
}

// Fused layer start: interval bounds + chain-start column-scale (both chains).
// TWO warps per row (interleaved halves), 4 rows per 256-thread block.
__global__ __launch_bounds__(256) void k_layer_start(
    const float* __restrict__ W, const float* __restrict__ bvec,
    const float* __restrict__ ub, const float* __restrict__ lb,
    const float* __restrict__ sus, const float* __restrict__ sui,
    const float* __restrict__ sls, const float* __restrict__ sli,
    const float* __restrict__ blayer,
    float* __restrict__ uo, float* __restrict__ lo,
    __half* __restrict__ A, float* __restrict__ Bias) {
    int wid = threadIdx.x >> 5, lane = threadIdx.x & 31;
    int rl = wid >> 1, half = wid & 1;
    int row = blockIdx.x * 4 + rl;               // grid exact: H/4 blocks
    __shared__ float red[4][8];                  // [rowLocal][half*4 + {su,sl,accu,accl}]
    const float4* wr = (const float4*)(W + (long)row * H);
    __half2* au = (__half2*)(A + (long)row * H);
    __half2* al = (__half2*)(A + (long)(row + H) * H);
    const float4* u4 = (const float4*)ub;
    const float4* l4 = (const float4*)lb;
    const float4* ps4 = (const float4*)sus;
    const float4* pi4 = (const float4*)sui;
    const float4* ns4 = (const float4*)sls;
    const float4* ni4 = (const float4*)sli;
    const float4* bl4 = (const float4*)blayer;
    float su = 0.0f, sl = 0.0f, accu = 0.0f, accl = 0.0f;
    for (int j = lane + half * 32; j < H / 4; j += 64) {
        float4 w = wr[j], u = u4[j], l = l4[j];
        float4 psv = ps4[j], piv = pi4[j], nsv = ns4[j], niv = ni4[j], blv = bl4[j];
        float p, n, oux, ouy, ouz, ouw, olx, oly, olz, olw;
        p = fmaxf(w.x, 0.0f); n = fminf(w.x, 0.0f);
        su += p * u.x + n * l.x; sl += p * l.x + n * u.x;
        oux = p * psv.x + n * nsv.x; accu += p * piv.x + n * niv.x + oux * blv.x;
        olx = p * nsv.x + n * psv.x; accl += p * niv.x + n * piv.x + olx * blv.x;
        p = fmaxf(w.y, 0.0f); n = fminf(w.y, 0.0f);
        su += p * u.y + n * l.y; sl += p * l.y + n * u.y;
        ouy = p * psv.y + n * nsv.y; accu += p * piv.y + n * niv.y + ouy * blv.y;
        oly = p * nsv.y + n * psv.y; accl += p * niv.y + n * piv.y + oly * blv.y;
        p = fmaxf(w.z, 0.0f); n = fminf(w.z, 0.0f);
        su += p * u.z + n * l.z; sl += p * l.z + n * u.z;
        ouz = p * psv.z + n * nsv.z; accu += p * piv.z + n * niv.z + ouz * blv.z;
        olz = p * nsv.z + n * psv.z; accl += p * niv.z + n * piv.z + olz * blv.z;
        p = fmaxf(w.w, 0.0f); n = fminf(w.w, 0.0f);
        su += p * u.w + n * l.w; sl += p * l.w + n * u.w;
        ouw = p * psv.w + n * nsv.w; accu += p * piv.w + n * niv.w + ouw * blv.w;
        olw = p * nsv.w + n * psv.w; accl += p * niv.w + n * piv.w + olw * blv.w;
        au[2 * j]     = __floats2half2_rn(oux, ouy);
        au[2 * j + 1] = __floats2half2_rn(ouz, ouw);
        al[2 * j]     = __floats2half2_rn(olx, oly);
        al[2 * j + 1] = __floats2half2_rn(olz, olw);
    }
    su = warp_reduce(su);
    sl = warp_reduce(sl);
    accu = warp_reduce(accu);
    accl = warp_reduce(accl);
    if (lane == 0) {
        red[rl][half * 4 + 0] = su;
        red[rl][half * 4 + 1] = sl;
        red[rl][half * 4 + 2] = accu;
        red[rl][half * 4 + 3] = accl;
    }
    __syncthreads();
    if (half == 0 && lane == 0) {
        float bb = bvec[row];
        uo[row] = red[rl][0] + red[rl][4] + bb;
        lo[row] = red[rl][1] + red[rl][5] + bb;
        Bias[row] = bb + red[rl][2] + red[rl][6];
        Bias[row + H] = bb + red[rl][3] + red[rl][7];
    }
}

// Fused chain end (layers 2/3): interval evaluation of BOTH chains for one neuron,
// bound refinement, SPU, post collapse. TWO warps per neuron, 4 neurons/block.
__global__ __launch_bounds__(256) void k_interval_spu(
    const float* __restrict__ W, int ld, const float* __restrict__ bias,
    const float* __restrict__ u0, const float* __restrict__ l0,
    const float* __restrict__ ubl, const float* __restrict__ lbl,
    float* __restrict__ us, float* __restrict__ ui,
    float* __restrict__ ls, float* __restrict__ li,
    float* __restrict__ pub, float* __restrict__ plb) {
    int wid = threadIdx.x >> 5, lane = threadIdx.x & 31;
    int rl = wid >> 1, half = wid & 1;
    int orow = blockIdx.x * 4 + rl;              // grid exact: H/4 blocks
    __shared__ float red[4][4];                  // [rowLocal][half*2 + {u,l}]
    const float4* wu = (const float4*)(W + (long)orow * ld);
    const float4* wl = (const float4*)(W + (long)(orow + H) * ld);
    const float4* u4 = (const float4*)u0;
    const float4* l4 = (const float4*)l0;
    float accu = 0.0f, accl = 0.0f;
    for (int j = lane + half * 32; j < DIN / 4; j += 64) {
        float4 a = wu[j], b = wl[j];
        float4 uv = u4[j], lv = l4[j];
        accu += fmaxf(a.x, 0.0f) * uv.x + fminf(a.x, 0.0f) * lv.x;
        accu += fmaxf(a.y, 0.0f) * uv.y + fminf(a.y, 0.0f) * lv.y;
        accu += fmaxf(a.z, 0.0f) * uv.z + fminf(a.z, 0.0f) * lv.z;
        accu += fmaxf(a.w, 0.0f) * uv.w + fminf(a.w, 0.0f) * lv.w;
        accl += fmaxf(b.x, 0.0f) * lv.x + fminf(b.x, 0.0f) * uv.x;
        accl += fmaxf(b.y, 0.0f) * lv.y + fminf(b.y, 0.0f) * uv.y;
        accl += fmaxf(b.z, 0.0f) * lv.z + fminf(b.z, 0.0f) * uv.z;
        accl += fmaxf(b.w, 0.0f) * lv.w + fminf(b.w, 0.0f) * uv.w;
    }
    accu = warp_reduce(accu);
    accl = warp_reduce(accl);
    if (lane == 0) { red[rl][half * 2] = accu; red[rl][half * 2 + 1] = accl; }
    __syncthreads();
    if (half == 0 && lane == 0) {
        float vu = red[rl][0] + red[rl][2] + bias[orow];
        float vl = red[rl][1] + red[rl][3] + bias[orow + H];
        float ub = fminf(ubl[orow], vu);
        float lb = fmaxf(lbl[orow], vl);
        float usv, uiv, lsv, liv, nub, nlb;
        spu_analyze(ub, lb, usv, uiv, lsv, liv, nub, nlb);
        us[orow] = usv; ui[orow] = uiv; ls[orow] = lsv; li[orow] = liv;
        float pvu = (usv >= 0.0f) ? vu : vl;
        float pvl = (lsv >= 0.0f) ? vl : vu;
        pub[orow] = fminf(nub, usv * pvu + uiv);
        plb[orow] = fmaxf(nlb, lsv * pvl + liv);
    }
}

// Layer 4 fused start: lower interval bound (LB4 init) + lower-chain colscale
// from ONE pass over w4. Warp-per-row, M=DOUT rows, all-lower chain.
__global__ __launch_bounds__(256) void k_affine_cs4(
    const float* __restrict__ W, const float* __restrict__ bvec,
    const float* __restrict__ ub, const float* __restrict__ lb,
    const float* __restrict__ sus, const float* __restrict__ sui,
    const float* __restrict__ sls, const float* __restrict__ sli,
    const float* __restrict__ blayer,
    __half* __restrict__ A, float* __restrict__ Bias, float* __restrict__ lb4) {
    int wid = threadIdx.x >> 5, lane = threadIdx.x & 31;
    int row = blockIdx.x * 8 + wid;
    if (row >= DOUT) return;
    const float4* wr = (const float4*)(W + (long)row * H);
    __half2* ah = (__half2*)(A + (long)row * H);
    const float4* u4 = (const float4*)ub;
    const float4* l4 = (const float4*)lb;
    const float4* ps = (const float4*)sls;   // lower chain
    const float4* pi = (const float4*)sli;
    const float4* ns = (const float4*)sus;
    const float4* ni = (const float4*)sui;
    const float4* bl = (const float4*)blayer;
    float sl = 0.0f, acc = 0.0f;
    for (int j = lane; j < H / 4; j += 32) {
        float4 w = wr[j], u = u4[j], l = l4[j];
        float4 psv = ps[j], piv = pi[j], nsv = ns[j], niv = ni[j], blv = bl[j];
        float4 o;
        float p, n;
        p = fmaxf(w.x, 0.0f); n = fminf(w.x, 0.0f); sl += p * l.x + n * u.x;
        o.x = p * psv.x + n * nsv.x; acc += p * piv.x + n * niv.x + o.x * blv.x;
        p = fmaxf(w.y, 0.0f); n = fminf(w.y, 0.0f); sl += p * l.y + n * u.y;
        o.y = p * psv.y + n * nsv.y; acc += p * piv.y + n * niv.y + o.y * blv.y;
        p = fmaxf(w.z, 0.0f); n = fminf(w.z, 0.0f); sl += p * l.z + n * u.z;
        o.z = p * psv.z + n * nsv.z; acc += p * piv.z + n * niv.z + o.z * blv.z;
        p = fmaxf(w.w, 0.0f); n = fminf(w.w, 0.0f); sl += p * l.w + n * u.w;
        o.w = p * psv.w + n * nsv.w; acc += p * piv.w + n * niv.w + o.w * blv.w;
        ah[2 * j]     = __floats2half2_rn(o.x, o.y);
        ah[2 * j + 1] = __floats2half2_rn(o.z, o.w);
    }
    sl = warp_reduce(sl);
    acc = warp_reduce(acc);
    if (lane == 0) {
        float bb = bvec[row];
        lb4[row] = sl + bb;
        Bias[row] = bb + acc;
    }
}

// Final interval evaluation at the input layer (layer-4 chain end); warp-per-row.
__global__ __launch_bounds__(256) void k_interval_f4(
    const float* __restrict__ W, int ld, const float* __restrict__ bias,
    const float* __restrict__ u0, const float* __restrict__ l0,
    float* __restrict__ lbio) {
    int wid = threadIdx.x >> 5, lane = threadIdx.x & 31;
    int row = blockIdx.x * 8 + wid;
    if (row >= DOUT) return;
    const float4* wr = (const float4*)(W + (long)row * ld);
    const float4* a4 = (const float4*)l0;
    const float4* c4p = (const float4*)u0;
    float acc = 0.0f;
    for (int j = lane; j < DIN / 4; j += 32) {
        float4 w = wr[j];
        float4 av = a4[j], cv = c4p[j];
        acc += fmaxf(w.x, 0.0f) * av.x + fminf(w.x, 0.0f) * cv.x;
        acc += fmaxf(w.y, 0.0f) * av.y + fminf(w.y, 0.0f) * cv.y;
        acc += fmaxf(w.z, 0.0f) * av.z + fminf(w.z, 0.0f) * cv.z;
        acc += fmaxf(w.w, 0.0f) * av.w + fminf(w.w, 0.0f) * cv.w;
    }
    acc = warp_reduce(acc);
    if (lane == 0) {
        float v = acc + bias[row];
        lbio[row] = fmaxf(lbio[row], v);
    }
}

// ---------------- fp16 GEMM via mma.sync (HMMA), 3-stage cp.async pipeline ------
// (exact R11/R13 configuration — known-good, do not perturb)
#define GSTRIDE 80
#define TILEB   (128 * GSTRIDE)
#define STAGEB  (2 * TILEB)            // A | B
#define NSTAGE  3
#define GEMM_SMEM (NSTAGE * STAGEB)    // 61440

struct GemmCtx {
    float acc[4][4][4];
    int rowBase, colBase, mbase, nbase, lr, lc2;
};

__device__ __forceinline__ void gemm_mainloop(
    GemmCtx& cx, char* dynsm,
    const __half* __restrict__ A, const __half* __restrict__ B, int M) {
    const int tid = threadIdx.x;
    const int wid = tid >> 5;
    const int lane = tid & 31;
    const uint32_t smbase = smem_u32(dynsm);
    const int wm = wid & 1, wn = wid >> 1;
    cx.mbase = wm * 64; cx.nbase = wn * 32;
    cx.lr = lane >> 2; cx.lc2 = 2 * (lane & 3);
#pragma unroll
    for (int mi = 0; mi < 4; mi++)
#pragma unroll
        for (int ni = 0; ni < 4; ni++)
#pragma unroll
            for (int t = 0; t < 4; t++) cx.acc[mi][ni][t] = 0.0f;

    const uint32_t aRowOff = (uint32_t)(cx.mbase + (lane & 15)) * GSTRIDE + (lane >> 4) * 16;
    const uint32_t bRowOff = (uint32_t)(cx.nbase + (lane & 7)) * GSTRIDE + ((lane >> 3) & 1) * 16;

    auto issue = [&](int c) {
        const int st = c % NSTAGE;
        const uint32_t base = smbase + st * STAGEB;
        const long k0 = (long)c * 32;
#pragma unroll
        for (int p = 0; p < 2; p++) {
            int u = tid + p * 256;
            int row = u >> 2, seg = u & 3;
            uint32_t so = base + row * GSTRIDE + seg * 16;
            long ka = k0 + seg * 8;
            int grow = cx.rowBase + row; if (grow > M - 1) grow = M - 1;
            cp16(so,         A + (long)grow * H + ka);
            int gn = cx.colBase + row;
            cp16(so + TILEB, B + (long)gn * H + ka);
        }
        asm volatile("cp.async.commit_group;");
    };

    const int NK = H / 32;
    issue(0);
    issue(1);
    for (int c = 0; c < NK; ++c) {
        if (c + 2 < NK) {
            issue(c + 2);
            asm volatile("cp.async.wait_group 2;");
        } else if (c + 1 < NK) {
            asm volatile("cp.async.wait_group 1;");
        } else {
            asm volatile("cp.async.wait_group 0;");
        }
        __syncthreads();
        const uint32_t sbu = smbase + (c % NSTAGE) * STAGEB;
        const uint32_t sAu = sbu + aRowOff;
        const uint32_t sBu = sbu + TILEB + bRowOff;
#pragma unroll
        for (int kk = 0; kk < 32; kk += 16) {
            const uint32_t kb = (uint32_t)(kk * 2);
            uint32_t bh[4][2];
#pragma unroll
            for (int ni = 0; ni < 4; ni++)
                ldsm_x2(sBu + (uint32_t)(ni * 8) * GSTRIDE + kb, bh[ni]);
#pragma unroll
            for (int mi = 0; mi < 4; mi++) {
                uint32_t ah[4];
                ldsm_x4(sAu + (uint32_t)(mi * 16) * GSTRIDE + kb, ah);
#pragma unroll
                for (int ni = 0; ni < 4; ni++)
                    mma16816h(cx.acc[mi][ni], ah, bh[ni]);
            }
        }
        __syncthreads();
    }
}

// Plain epilogue: fp32 C (used for the last GEMM of a chain).
__global__ __launch_bounds__(256) void gemm_mma(
    const __half* __restrict__ A, const __half* __restrict__ B,
    float* __restrict__ C, int M, int ldc) {
    extern __shared__ char dynsm[];
    GemmCtx cx;
    cx.rowBase = blockIdx.y * 128;
    cx.colBase = blockIdx.x * 128;
    gemm_mainloop(cx, dynsm, A, B, M);
#pragma unroll
    for (int mi = 0; mi < 4; mi++) {
        int gr0 = cx.rowBase + cx.mbase + mi * 16 + cx.lr;
#pragma unroll
        for (int ni = 0; ni < 4; ni++) {
            int gc = cx.colBase + cx.nbase + ni * 8 + cx.lc2;
            if (gr0 < M) {
                float2 v = make_float2(cx.acc[mi][ni][0], cx.acc[mi][ni][1]);
                *(float2*)(C + (long)gr0 * ldc + gc) = v;
            }
            if (gr0 + 8 < M) {
                float2 v = make_float2(cx.acc[mi][ni][2], cx.acc[mi][ni][3]);
                *(float2*)(C + (long)(gr0 + 8) * ldc + gc) = v;
            }
        }
    }
}

// Fused colscale epilogue: applies the next SPU diagonal pass to the accumulators,
// writes the fp16 A operand for the next GEMM, and atomically accumulates the
// per-row bias contribution (quad-reduced) into the running chain bias.
__global__ __launch_bounds__(256) void gemm_mma_cs(
    const __half* __restrict__ A, const __half* __restrict__ B,
    const float* __restrict__ sus, const float* __restrict__ sui,
    const float* __restrict__ sls, const float* __restrict__ sli,
    const float* __restrict__ blayer,
    __half* __restrict__ Ao, float* __restrict__ Bias, int M, int Mu) {
    extern __shared__ char dynsm[];
    GemmCtx cx;
    cx.rowBase = blockIdx.y * 128;
    cx.colBase = blockIdx.x * 128;
    gemm_mainloop(cx, dynsm, A, B, M);

    const bool up = cx.rowBase < Mu;    // Mu multiple of 128 (or 0) -> CTA-uniform
    const float* ps = up ? sus : sls;
    const float* pi = up ? sui : sli;
    const float* ns = up ? sls : sus;
    const float* ni_ = up ? sli : sui;
    const int lane = threadIdx.x & 31;

#pragma unroll
    for (int mi = 0; mi < 4; mi++) {
        int gr0 = cx.rowBase + cx.mbase + mi * 16 + cx.lr;
        int gr1 = gr0 + 8;
        float rs0 = 0.0f, rs1 = 0.0f;
#pragma unroll
        for (int ni = 0; ni < 4; ni++) {
            int gc = cx.colBase + cx.nbase + ni * 8 + cx.lc2;
            float s0 = ps[gc], s1 = ps[gc + 1];
            float i0 = pi[gc], i1 = pi[gc + 1];
            float t0 = ns[gc], t1 = ns[gc + 1];
            float u0v = ni_[gc], u1v = ni_[gc + 1];
            float b0 = blayer[gc], b1 = blayer[gc + 1];
            {
                float v0 = cx.acc[mi][ni][0], v1 = cx.acc[mi][ni][1];
                float p0 = fmaxf(v0, 0.0f), n0 = fminf(v0, 0.0f);
                float p1 = fmaxf(v1, 0.0f), n1 = fminf(v1, 0.0f);
                float o0 = p0 * s0 + n0 * t0;
                float o1 = p1 * s1 + n1 * t1;
                rs0 += p0 * i0 + n0 * u0v + o0 * b0 + p1 * i1 + n1 * u1v + o1 * b1;
                if (gr0 < M)
                    *(__half2*)(Ao + (long)gr0 * H + gc) = __floats2half2_rn(o0, o1);
            }
            {
                float v0 = cx.acc[mi][ni][2], v1 = cx.acc[mi][ni][3];
                float p0 = fmaxf(v0, 0.0f), n0 = fminf(v0, 0.0f);
                float p1 = fmaxf(v1, 0.0f), n1 = fminf(v1, 0.0f);
                float o0 = p0 * s0 + n0 * t0;
                float o1 = p1 * s1 + n1 * t1;
                rs1 += p0 * i0 + n0 * u0v + o0 * b0 + p1 * i1 + n1 * u1v + o1 * b1;
                if (gr1 < M)
                    *(__half2*)(Ao + (long)gr1 * H + gc) = __floats2half2_rn(o0, o1);
            }
        }
        rs0 += __shfl_xor_sync(0xffffffffu, rs0, 1);
        rs0 += __shfl_xor_sync(0xffffffffu, rs0, 2);
        rs1 += __shfl_xor_sync(0xffffffffu, rs1, 1);
        rs1 += __shfl_xor_sync(0xffffffffu, rs1, 2);
        if ((lane & 3) == 0) {
            if (gr0 < M) atomicAdd(Bias + gr0, rs0);
            if (gr1 < M) atomicAdd(Bias + gr1, rs1);
        }
    }
}

__global__ void k_final_min(const float* __restrict__ lb4, float* __restrict__ out) {
    if (threadIdx.x == 0) {
        float m = lb4[0];
#pragma unroll
        for (int i = 1; i < DOUT; i++) m = fminf(m, lb4[i]);
        out[0] = m;
    }
}

// ---------------- host orchestration ----------------
extern "C" void kernel_launch(void* const* d_in, const int* in_sizes, int n_in,
                              void* d_out, int out_size) {
    (void)in_sizes; (void)n_in; (void)out_size;
    const float* inputs = (const float*)d_in[0];
    const float* eps    = (const float*)d_in[1];
    const float* w1 = (const float*)d_in[2]; const float* b1 = (const float*)d_in[3];
    const float* w2 = (const float*)d_in[4]; const float* b2 = (const float*)d_in[5];
    const float* w3 = (const float*)d_in[6]; const float* b3 = (const float*)d_in[7];
    const float* w4 = (const float*)d_in[8]; const float* b4 = (const float*)d_in[9];
    float* out = (float*)d_out;

    cudaFuncSetAttribute(gemm_mma,    cudaFuncAttributeMaxDynamicSharedMemorySize, GEMM_SMEM);
    cudaFuncSetAttribute(gemm_mma_cs, cudaFuncAttributeMaxDynamicSharedMemorySize, GEMM_SMEM);

    float *U0, *L0, *UBL, *LBL, *SUS, *SUI, *SLS, *SLI, *PUB, *PLB, *LB4;
    float *W0, *BIAS;
    __half *A1, *A2, *T1F, *T2F, *T3F;
    cudaGetSymbolAddress((void**)&U0, g_u0);
    cudaGetSymbolAddress((void**)&L0, g_l0);
    cudaGetSymbolAddress((void**)&UBL, g_ubL);
    cudaGetSymbolAddress((void**)&LBL, g_lbL);
    cudaGetSymbolAddress((void**)&SUS, g_sus);
    cudaGetSymbolAddress((void**)&SUI, g_sui);
    cudaGetSymbolAddress((void**)&SLS, g_sls);
    cudaGetSymbolAddress((void**)&SLI, g_sli);
    cudaGetSymbolAddress((void**)&PUB, g_pub);
    cudaGetSymbolAddress((void**)&PLB, g_plb);
    cudaGetSymbolAddress((void**)&LB4, g_lb4);
    cudaGetSymbolAddress((void**)&W0, g_W0);
    cudaGetSymbolAddress((void**)&BIAS, g_Bias);
    cudaGetSymbolAddress((void**)&A1, g_A1);
    cudaGetSymbolAddress((void**)&A2, g_A2);
    cudaGetSymbolAddress((void**)&T1F, g_T1f);
    cudaGetSymbolAddress((void**)&T2F, g_T2f);
    cudaGetSymbolAddress((void**)&T3F, g_T3f);

    // transposed fp16 weights (B operands) — one merged launch
    k_transpose_all<<<dim3(64, 64, 3), dim3(32, 8)>>>(w1, w2, w3, T1F, T2F, T3F);

    // input box (normalized)
    k_init_bounds<<<(DIN + 255) / 256, 256>>>(inputs, eps, U0, L0);

    // ---- layer 1 (fused affine interval + SPU + post collapse) ----
    k_affine_spu<<<H / 4, 256>>>(w1, b1, U0, L0,
                                 SUS + 0 * H, SUI + 0 * H, SLS + 0 * H, SLI + 0 * H,
                                 PUB + 0 * H, PLB + 0 * H);

    // ---- layer 2 ----
    k_layer_start<<<H / 4, 256>>>(w2, b2, PUB + 0 * H, PLB + 0 * H,
                                  SUS + 0 * H, SUI + 0 * H, SLS + 0 * H, SLI + 0 * H,
                                  b1, UBL + 1 * H, LBL + 1 * H, A1, BIAS);
    {
        dim3 g(NPAD1 / 128, (2 * H) / 128);
        gemm_mma<<<g, 256, GEMM_SMEM>>>(A1, T1F, W0, 2 * H, NPAD1);
    }
    k_interval_spu<<<H / 4, 256>>>(W0, NPAD1, BIAS, U0, L0,
                                   UBL + 1 * H, LBL + 1 * H,
                                   SUS + 1 * H, SUI + 1 * H, SLS + 1 * H, SLI + 1 * H,
                                   PUB + 1 * H, PLB + 1 * H);

    // ---- layer 3 ----
    k_layer_start<<<H / 4, 256>>>(w3, b3, PUB + 1 * H, PLB + 1 * H,
                                  SUS + 1 * H, SUI + 1 * H, SLS + 1 * H, SLI + 1 * H,
                                  b2, UBL + 2 * H, LBL + 2 * H, A1, BIAS);
    {
        dim3 g(H / 128, (2 * H) / 128);
        gemm_mma_cs<<<g, 256, GEMM_SMEM>>>(A1, T2F,
                                           SUS + 0 * H, SUI + 0 * H, SLS + 0 * H, SLI + 0 * H,
                                           b1, A2, BIAS, 2 * H, H);
        dim3 g2(NPAD1 / 128, (2 * H) / 128);
        gemm_mma<<<g2, 256, GEMM_SMEM>>>(A2, T1F, W0, 2 * H, NPAD1);
    }
    k_interval_spu<<<H / 4, 256>>>(W0, NPAD1, BIAS, U0, L0,
                                   UBL + 2 * H, LBL + 2 * H,
                                   SUS + 2 * H, SUI + 2 * H, SLS + 2 * H, SLI + 2 * H,
                                   PUB + 2 * H, PLB + 2 * H);

    // ---- layer 4 (only the lower bound matters for the output) ----
    k_affine_cs4<<<(DOUT + 7) / 8, 256>>>(w4, b4, PUB + 2 * H, PLB + 2 * H,
                                          SUS + 2 * H, SUI + 2 * H, SLS + 2 * H, SLI + 2 * H,
                                          b3, A1, BIAS, LB4);
    {
        dim3 g(H / 128, 1);
        gemm_mma_cs<<<g, 256, GEMM_SMEM>>>(A1, T3F,
                                           SUS + 1 * H, SUI + 1 * H, SLS + 1 * H, SLI + 1 * H,
                                           b2, A2, BIAS, DOUT, 0);
        gemm_mma_cs<<<g, 256, GEMM_SMEM>>>(A2, T2F,
                                           SUS + 0 * H, SUI + 0 * H, SLS + 0 * H, SLI + 0 * H,
                                           b1, A1, BIAS, DOUT, 0);
        dim3 g2(NPAD1 / 128, 1);
        gemm_mma<<<g2, 256, GEMM_SMEM>>>(A1, T1F, W0, DOUT, NPAD1);
    }
    k_interval_f4<<<(DOUT + 7) / 8, 256>>>(W0, NPAD1, BIAS, U0, L0, LB4);

    k_final_min<<<1, 32>>>(LB4, out);
}